// round 17
// baseline (speedup 1.0000x reference)
#include <cuda_runtime.h>
#include <cuda_fp16.h>
#include <math.h>

#define N_NODES 100000
#define D 64
#define E_MAX 1600000
#define CHUNK 1024
#define NCHUNK ((N_NODES + CHUNK - 1) / CHUNK)   // 98
#define INP 132   // inT row stride (floats): multiple of 4 -> float4-aligned rows;
                  // (2l*132 + r) % 32 = (8l+r)%32 -> 8-way STS conflict (acceptable)

// ---- scratch (__device__ globals: allocation-free per harness rules) ----
__device__ __half g_mH[(size_t)N_NODES * D];    // fp16 message buffer (layer-1 GEMM out)
__device__ __half g_mB[(size_t)N_NODES * D];    // fp16 message buffer (fused agg1+gemm2 out)
__device__ float  g_r[N_NODES];                 // per-node scalar (layer-3 collapse)
__device__ float  g_ws[D];                      // colsum(W3)
__device__ float  g_bsum[1];                    // sum(b3)
__device__ int    g_cnt[N_NODES];               // zeroed by final_kernel (prev call)
__device__ int    g_rowptr[N_NODES];
__device__ int    g_cursor[N_NODES];
__device__ int    g_eidx[E_MAX];
__device__ int    g_csum[128];                  // lookback slots; zeroed by final_kernel

// ---- side stream + events for graph fork (created at load; never freed) ----
static cudaStream_t g_s2;
static cudaEvent_t  g_evFork, g_evJoin;
static bool g_streamOk = [](){
    if (cudaStreamCreateWithFlags(&g_s2, cudaStreamNonBlocking) != cudaSuccess) return false;
    if (cudaEventCreateWithFlags(&g_evFork, cudaEventDisableTiming) != cudaSuccess) return false;
    if (cudaEventCreateWithFlags(&g_evJoin, cudaEventDisableTiming) != cudaSuccess) return false;
    return true;
}();

// ---- PDL: grid-dependency sync at kernel entry (NO explicit trigger — see R10) ----
__device__ __forceinline__ void dep_sync() {
#if defined(__CUDA_ARCH__) && __CUDA_ARCH__ >= 900
    cudaGridDependencySynchronize();
#endif
}

// ---- packed f32x2 helpers (Blackwell FFMA2; PTX-only) ----
__device__ __forceinline__ void fma_x2(unsigned long long& acc,
                                       unsigned long long a, unsigned long long b) {
    asm("fma.rn.f32x2 %0, %1, %2, %0;" : "+l"(acc) : "l"(a), "l"(b));
}
__device__ __forceinline__ unsigned long long bcast_x2(float v) {
    unsigned long long r;
    asm("mov.b64 %0, {%1, %1};" : "=l"(r) : "r"(__float_as_uint(v)));
    return r;
}
__device__ __forceinline__ float2 unpack_x2(unsigned long long v) {
    unsigned int lo, hi;
    asm("mov.b64 {%0, %1}, %2;" : "=r"(lo), "=r"(hi) : "l"(v));
    return make_float2(__uint_as_float(lo), __uint_as_float(hi));
}

// ---- shared 4-edge-unroll gather body: v0,v1 = sum of m[src] cols (2l, 2l+1) ----
#define AGG_GATHER_BODY(M)                                                    \
    float a0 = 0.f, a1 = 0.f, b0 = 0.f, b1 = 0.f;                             \
    float c0 = 0.f, c1 = 0.f, d0 = 0.f, d1 = 0.f;                             \
    int k = 0;                                                                \
    for (; k + 4 <= n; k += 4) {                                              \
        int s0 = __ldg(g_eidx + start + k + 0);                               \
        int s1 = __ldg(g_eidx + start + k + 1);                               \
        int s2 = __ldg(g_eidx + start + k + 2);                               \
        int s3 = __ldg(g_eidx + start + k + 3);                               \
        float2 u0 = __half22float2(__ldg(M + (size_t)s0 * 32 + l));           \
        float2 u1 = __half22float2(__ldg(M + (size_t)s1 * 32 + l));           \
        float2 u2 = __half22float2(__ldg(M + (size_t)s2 * 32 + l));           \
        float2 u3 = __half22float2(__ldg(M + (size_t)s3 * 32 + l));           \
        a0 += u0.x; a1 += u0.y;                                               \
        b0 += u1.x; b1 += u1.y;                                               \
        c0 += u2.x; c1 += u2.y;                                               \
        d0 += u3.x; d1 += u3.y;                                               \
    }                                                                         \
    for (; k < n; k++) {                                                      \
        int s = __ldg(g_eidx + start + k);                                    \
        float2 u = __half22float2(__ldg(M + (size_t)s * 32 + l));             \
        a0 += u.x; a1 += u.y;                                                 \
    }                                                                         \
    float v0 = (a0 + b0) + (c0 + d0);                                         \
    float v1 = (a1 + b1) + (c1 + d1);

// ============================ CSR build ============================

// block 0: constants + d_out zero; blocks 1..: degree histogram (REDG), 4 edges/thread.
__global__ void degree_kernel(const int4* __restrict__ dst4, int E4,
                              const float* __restrict__ W3, const float* __restrict__ b3,
                              float* __restrict__ out, int out_n) {
    dep_sync();
    int t = threadIdx.x;
    if (blockIdx.x == 0) {
        if (t < D) {
            float s = 0.f;
#pragma unroll
            for (int j = 0; j < D; j++) s += W3[j * D + t];
            g_ws[t] = s;
        } else if (t == D) {
            float bs = 0.f;
#pragma unroll
            for (int j = 0; j < D; j++) bs += b3[j];
            g_bsum[0] = bs;
        } else if (t >= 96 && t < 96 + out_n) {
            out[t - 96] = 0.f;
        }
        return;
    }
    int i = (blockIdx.x - 1) * blockDim.x + t;
    if (i < E4) {
        int4 d = dst4[i];
        atomicAdd(&g_cnt[d.x], 1);
        atomicAdd(&g_cnt[d.y], 1);
        atomicAdd(&g_cnt[d.z], 1);
        atomicAdd(&g_cnt[d.w], 1);
    }
}

// single-pass exclusive scan with decoupled lookback (98 blocks, wave-1 resident)
__global__ __launch_bounds__(256) void scanapply_kernel() {
    dep_sync();
    int b = blockIdx.x, t = threadIdx.x;
    int base = b * CHUNK + t * 4;
    int c[4];
    int ts = 0;
#pragma unroll
    for (int i = 0; i < 4; i++) {
        int idx = base + i;
        c[i] = (idx < N_NODES) ? g_cnt[idx] : 0;
        ts += c[i];
    }
    int lane = t & 31, wid = t >> 5;
    int incl = ts;
#pragma unroll
    for (int d = 1; d < 32; d <<= 1) {
        int u = __shfl_up_sync(0xffffffffu, incl, d);
        if (lane >= d) incl += u;
    }
    __shared__ int wsum[8], woff[8];
    __shared__ int rsum[8];
    __shared__ int s_prefix;
    if (lane == 31) wsum[wid] = incl;
    __syncthreads();
    if (t == 0) {
        int acc = 0;
#pragma unroll
        for (int i = 0; i < 8; i++) { woff[i] = acc; acc += wsum[i]; }
        *(volatile int*)&g_csum[b] = acc + 1;   // publish (+1: 0 = not ready)
    }
    __syncthreads();
    int part = 0;
    if (t < b) {
        volatile int* p = &g_csum[t];
        int v;
        do { v = *p; } while (v == 0);
        part = v - 1;
    }
#pragma unroll
    for (int off = 16; off; off >>= 1) part += __shfl_down_sync(0xffffffffu, part, off);
    if (lane == 0) rsum[wid] = part;
    __syncthreads();
    if (t == 0) {
        int acc = 0;
#pragma unroll
        for (int i = 0; i < 8; i++) acc += rsum[i];
        s_prefix = acc;
    }
    __syncthreads();
    int excl = incl - ts + woff[wid] + s_prefix;
#pragma unroll
    for (int i = 0; i < 4; i++) {
        int idx = base + i;
        if (idx < N_NODES) { g_rowptr[idx] = excl; g_cursor[idx] = excl; }
        excl += c[i];
    }
}

__global__ void fill_kernel(const int* __restrict__ src, const int* __restrict__ dst, int E) {
    dep_sync();
    int e = blockIdx.x * blockDim.x + threadIdx.x;
    if (e < E) {
        int s = __ldg(src + e);
        int pos = atomicAdd(&g_cursor[dst[e]], 1);
        g_eidx[pos] = s;
    }
}

// ============================ f32x2 register-blocked GEMM (layer 1) ============================
__global__ __launch_bounds__(256) void gemm_rb_kernel(const float* __restrict__ in_,
                                                      const float* __restrict__ W,
                                                      const float* __restrict__ b,
                                                      __half2* __restrict__ out) {
    dep_sync();
    __shared__ float inT[D][128];        // 32KB, [k][row]
    __shared__ float WsT[D][D + 2];      // ~16.5KB, [k][col] (transposed, padded)
    __shared__ float bs[D];
    int t = threadIdx.x;
    for (int i = t; i < D * D; i += 256) {
        int j = i >> 6, k = i & 63;
        WsT[k][j] = W[i];
    }
    if (t < D) bs[t] = b[t];

    int row0 = blockIdx.x * 128;
    int r = t >> 1, half = t & 1;
    int grow = row0 + r;
    const float4* inF = (const float4*)(in_ + (size_t)grow * D + half * 32);
    if (grow < N_NODES) {
#pragma unroll
        for (int i = 0; i < 8; i++) {
            float4 v = inF[i];
            inT[half * 32 + 4 * i + 0][r] = v.x;
            inT[half * 32 + 4 * i + 1][r] = v.y;
            inT[half * 32 + 4 * i + 2][r] = v.z;
            inT[half * 32 + 4 * i + 3][r] = v.w;
        }
    } else {
#pragma unroll
        for (int i = 0; i < 32; i++) inT[half * 32 + i][r] = 0.f;
    }
    __syncthreads();

    int w = t >> 5, l = t & 31;
    int colBase = w * 8;
    unsigned long long acc[4][4];
#pragma unroll
    for (int i = 0; i < 4; i++)
#pragma unroll
        for (int j = 0; j < 4; j++) acc[i][j] = 0ull;

#pragma unroll 4
    for (int k = 0; k < D; k++) {
        float4 a = *(const float4*)&inT[k][l * 4];
        unsigned long long w0 = *(const unsigned long long*)&WsT[k][colBase + 0];
        unsigned long long w1 = *(const unsigned long long*)&WsT[k][colBase + 2];
        unsigned long long w2 = *(const unsigned long long*)&WsT[k][colBase + 4];
        unsigned long long w3 = *(const unsigned long long*)&WsT[k][colBase + 6];
        unsigned long long ax = bcast_x2(a.x), ay = bcast_x2(a.y);
        unsigned long long az = bcast_x2(a.z), aw = bcast_x2(a.w);
        fma_x2(acc[0][0], ax, w0); fma_x2(acc[0][1], ax, w1);
        fma_x2(acc[0][2], ax, w2); fma_x2(acc[0][3], ax, w3);
        fma_x2(acc[1][0], ay, w0); fma_x2(acc[1][1], ay, w1);
        fma_x2(acc[1][2], ay, w2); fma_x2(acc[1][3], ay, w3);
        fma_x2(acc[2][0], az, w0); fma_x2(acc[2][1], az, w1);
        fma_x2(acc[2][2], az, w2); fma_x2(acc[2][3], az, w3);
        fma_x2(acc[3][0], aw, w0); fma_x2(acc[3][1], aw, w1);
        fma_x2(acc[3][2], aw, w2); fma_x2(acc[3][3], aw, w3);
    }

#pragma unroll
    for (int i = 0; i < 4; i++) {
        int orow = row0 + l * 4 + i;
        if (orow < N_NODES) {
            __half2 o[4];
#pragma unroll
            for (int j = 0; j < 4; j++) {
                float2 v = unpack_x2(acc[i][j]);
                o[j] = __floats2half2_rn(v.x + bs[colBase + 2 * j],
                                         v.y + bs[colBase + 2 * j + 1]);
            }
            *(uint4*)&out[(size_t)orow * 32 + colBase / 2] = *(const uint4*)o;
        }
    }
}

// ============================ FUSED agg1 + gemm2 ============================
// Phase A: block gathers+tanh's its 128 nodes (warp w: nodes w*16..w*16+15,
// lane l owns cols 2l, 2l+1), staging fp32 results transposed into inT.
// Phase B: register-blocked FFMA2 GEMM (identical to gemm_rb) -> fp16 out.
__global__ __launch_bounds__(256) void agg_gemm_kernel(const __half2* __restrict__ m,
                                                       const float* __restrict__ W,
                                                       const float* __restrict__ b,
                                                       __half2* __restrict__ out) {
    dep_sync();
    __shared__ float inT[D][INP];        // stride 132: float4-aligned rows
    __shared__ float WsT[D][D + 2];      // ~16.5KB
    __shared__ float bs[D];
    int t = threadIdx.x;
    for (int i = t; i < D * D; i += 256) {
        int j = i >> 6, k = i & 63;
        WsT[k][j] = W[i];
    }
    if (t < D) bs[t] = b[t];

    int row0 = blockIdx.x * 128;
    int w = t >> 5, l = t & 31;

    // --- Phase A: gather + tanh for this block's 128 nodes ---
    for (int i = 0; i < 16; i++) {
        int r = w * 16 + i;              // local row 0..127
        int node = row0 + r;
        float t0 = 0.f, t1 = 0.f;
        if (node < N_NODES) {
            int start = g_rowptr[node];
            int n = g_cnt[node];
            AGG_GATHER_BODY(m)
            t0 = tanhf(v0);
            t1 = tanhf(v1);
        }
        inT[2 * l][r]     = t0;
        inT[2 * l + 1][r] = t1;
    }
    __syncthreads();

    // --- Phase B: GEMM (h @ W2^T + b2) ---
    int colBase = w * 8;
    unsigned long long acc[4][4];
#pragma unroll
    for (int i = 0; i < 4; i++)
#pragma unroll
        for (int j = 0; j < 4; j++) acc[i][j] = 0ull;

#pragma unroll 4
    for (int k = 0; k < D; k++) {
        float4 a = *(const float4*)&inT[k][l * 4];
        unsigned long long w0 = *(const unsigned long long*)&WsT[k][colBase + 0];
        unsigned long long w1 = *(const unsigned long long*)&WsT[k][colBase + 2];
        unsigned long long w2 = *(const unsigned long long*)&WsT[k][colBase + 4];
        unsigned long long w3 = *(const unsigned long long*)&WsT[k][colBase + 6];
        unsigned long long ax = bcast_x2(a.x), ay = bcast_x2(a.y);
        unsigned long long az = bcast_x2(a.z), aw = bcast_x2(a.w);
        fma_x2(acc[0][0], ax, w0); fma_x2(acc[0][1], ax, w1);
        fma_x2(acc[0][2], ax, w2); fma_x2(acc[0][3], ax, w3);
        fma_x2(acc[1][0], ay, w0); fma_x2(acc[1][1], ay, w1);
        fma_x2(acc[1][2], ay, w2); fma_x2(acc[1][3], ay, w3);
        fma_x2(acc[2][0], az, w0); fma_x2(acc[2][1], az, w1);
        fma_x2(acc[2][2], az, w2); fma_x2(acc[2][3], az, w3);
        fma_x2(acc[3][0], aw, w0); fma_x2(acc[3][1], aw, w1);
        fma_x2(acc[3][2], aw, w2); fma_x2(acc[3][3], aw, w3);
    }

#pragma unroll
    for (int i = 0; i < 4; i++) {
        int orow = row0 + l * 4 + i;
        if (orow < N_NODES) {
            __half2 o[4];
#pragma unroll
            for (int j = 0; j < 4; j++) {
                float2 v = unpack_x2(acc[i][j]);
                o[j] = __floats2half2_rn(v.x + bs[colBase + 2 * j],
                                         v.y + bs[colBase + 2 * j + 1]);
            }
            *(uint4*)&out[(size_t)orow * 32 + colBase / 2] = *(const uint4*)o;
        }
    }
}

// ============================ layer-2 agg + layer-3 collapse ============================

__global__ __launch_bounds__(256) void agg_rsum_kernel(const __half2* __restrict__ m) {
    dep_sync();
    int node = (blockIdx.x * blockDim.x + threadIdx.x) >> 5;
    int l = threadIdx.x & 31;
    if (node < N_NODES) {
        int start = g_rowptr[node];
        int n = g_cnt[node];
        AGG_GATHER_BODY(m)
        float s = tanhf(v0) * g_ws[2 * l] + tanhf(v1) * g_ws[2 * l + 1];
#pragma unroll
        for (int off = 16; off; off >>= 1) s += __shfl_down_sync(0xffffffffu, s, off);
        if (l == 0) g_r[node] = s + g_bsum[0];
    }
}

// final: per node, sum r over incoming edges (CSR), bin by graph.
// Also cleans g_cnt/g_csum for the next replay.
__global__ __launch_bounds__(256) void final_kernel(const int* __restrict__ n2g,
                                                    float* __restrict__ out, int E) {
    dep_sync();
    __shared__ float bins[8];
    int t = threadIdx.x;
    if (t < 8) bins[t] = 0.f;
    __syncthreads();
    int node = (blockIdx.x * blockDim.x + t) >> 5;
    int l = t & 31;
    if (node < N_NODES) {
        int start = g_rowptr[node];
        int end = (node + 1 < N_NODES) ? __ldg(g_rowptr + node + 1) : E;
        float s = 0.f;
        for (int e = start + l; e < end; e += 32) s += __ldg(g_r + __ldg(g_eidx + e));
#pragma unroll
        for (int off = 16; off; off >>= 1) s += __shfl_down_sync(0xffffffffu, s, off);
        if (l == 0) atomicAdd(&bins[__ldg(n2g + node)], s);
    }
    __syncthreads();
    if (t < 8) atomicAdd(&out[t], bins[t]);
    // cleanup for next call (final never reads g_cnt / g_csum)
    for (int i = blockIdx.x * blockDim.x + t; i < N_NODES; i += gridDim.x * blockDim.x)
        g_cnt[i] = 0;
    if (blockIdx.x == 0 && t >= 128 && t < 256) g_csum[t - 128] = 0;
}

// ============================ launch ============================

template<typename... Args>
static void launch_pdl(void* func, dim3 grid, dim3 block, cudaStream_t s, Args*... args) {
    void* argv[] = { (void*)args... };
    cudaLaunchConfig_t cfg = {};
    cfg.gridDim = grid; cfg.blockDim = block; cfg.stream = s;
    cudaLaunchAttribute attr[1];
    attr[0].id = cudaLaunchAttributeProgrammaticStreamSerialization;
    attr[0].val.programmaticStreamSerializationAllowed = 1;
    cfg.attrs = attr; cfg.numAttrs = 1;
    cudaLaunchKernelExC(&cfg, func, argv);
}

extern "C" void kernel_launch(void* const* d_in, const int* in_sizes, int n_in,
                              void* d_out, int out_size) {
    const float* x   = (const float*)d_in[0];
    const float* W1  = (const float*)d_in[1];
    const float* b1  = (const float*)d_in[2];
    const float* W2  = (const float*)d_in[3];
    const float* b2  = (const float*)d_in[4];
    const float* W3  = (const float*)d_in[5];
    const float* b3  = (const float*)d_in[6];
    const int*   src = (const int*)d_in[7];
    const int*   dst = (const int*)d_in[8];
    const int*   n2g = (const int*)d_in[9];
    float* out = (float*)d_out;

    int E  = in_sizes[7];
    int E4 = E / 4;                       // E = 1.6M, divisible by 4
    int nb_edges = (E + 255) / 256;
    int deg_blocks = 1 + (E4 + 255) / 256;
    int gemm_blocks = (N_NODES + 127) / 128;
    int warp_blocks = (N_NODES * 32 + 255) / 256;

    __half* mH;  __half* mB;
    cudaGetSymbolAddress((void**)&mH, g_mH);
    cudaGetSymbolAddress((void**)&mB, g_mB);

    __half2* mH2 = (__half2*)mH;
    const __half2* mH2c = (const __half2*)mH;
    __half2* mB2 = (__half2*)mB;
    const __half2* mB2c = (const __half2*)mB;
    const int4* dst4 = (const int4*)dst;

    if (g_streamOk) {
        cudaEventRecord(g_evFork, 0);
        cudaStreamWaitEvent(g_s2, g_evFork, 0);
        gemm_rb_kernel<<<gemm_blocks, 256, 0, g_s2>>>(x, W1, b1, mH2);
        cudaEventRecord(g_evJoin, g_s2);

        launch_pdl((void*)degree_kernel, deg_blocks, 256, 0,
                   &dst4, &E4, &W3, &b3, &out, &out_size);
        launch_pdl((void*)scanapply_kernel, NCHUNK, 256, 0);
        launch_pdl((void*)fill_kernel, nb_edges, 256, 0, &src, &dst, &E);

        cudaStreamWaitEvent(0, g_evJoin, 0);   // join before fused agg1+gemm2
    } else {
        degree_kernel<<<deg_blocks, 256>>>(dst4, E4, W3, b3, out, out_size);
        scanapply_kernel<<<NCHUNK, 256>>>();
        fill_kernel<<<nb_edges, 256>>>(src, dst, E);
        gemm_rb_kernel<<<gemm_blocks, 256>>>(x, W1, b1, mH2);
    }

    // fused layer-1-agg + layer-2-GEMM: gathers from g_mH, writes g_mB (no alias)
    launch_pdl((void*)agg_gemm_kernel, gemm_blocks, 256, 0, &mH2c, &W2, &b2, &mB2);
    launch_pdl((void*)agg_rsum_kernel, warp_blocks, 256, 0, &mB2c);
    launch_pdl((void*)final_kernel, warp_blocks, 256, 0, &n2g, &out, &E);
}